// round 2
// baseline (speedup 1.0000x reference)
#include <cuda_runtime.h>
#include <cuda_bf16.h>

#define B 128
#define S 256
#define C 64

// Per-batch (free_energy - path_energy); reduced by crf_reduce.
__device__ float g_scratch[B];

__global__ __launch_bounds__(128, 1) void crf_main(
    const float* __restrict__ emis,   // [B, S, C]
    const int*   __restrict__ tags,   // [B, S]
    const float* __restrict__ mask,   // [B, S]
    const float* __restrict__ U)      // [C, C]
{
    const int b   = blockIdx.x;
    const int tid = threadIdx.x;
    const int j   = tid & 63;   // column owned
    const int h   = tid >> 6;   // i-range half: h=0 -> i in [0,32), h=1 -> [32,64)

    __shared__ __align__(16) float sh_e[2][C];  // double-buffered normalized alpha (linear space)
    __shared__ float sh_p[C];                   // partial sums from h=1 half
    __shared__ float sh_red[128];               // path-energy partials

    const float* embase = emis + (size_t)b * S * C;
    const float* mbase  = mask + b * S;
    const int*   tbase  = tags + b * S;

    // ---------------- path energy partials (2 timesteps per thread) ----------------
    float pp = 0.f;
#pragma unroll
    for (int q = 0; q < 2; ++q) {
        int   s  = 2 * tid + q;
        int   tg = tbase[s];
        float m  = mbase[s];
        int   tm = (int)((float)tg * m);          // matches (tags*mask).astype(int32)
        pp += embase[s * C + tm] * m;
        if (s >= 1) {
            int tp = tbase[s - 1];
            pp += U[tp * C + tg] * m;             // raw tags for transition term
        }
    }
    sh_red[tid] = pp;

    // ---------------- exp(U) column slice into registers ----------------
    float uexp[32];
#pragma unroll
    for (int k = 0; k < 32; ++k)
        uexp[k] = __expf(U[(h * 32 + k) * C + j]);

    // ---------------- init: alpha_0 = emissions[:,0,:], stored as e = exp(alpha) ----------------
    if (h == 0)
        sh_e[0][j] = __expf(embase[j]);
    __syncthreads();

    float base = 0.f;   // cumulative log-shift (h==0 threads; all identical)
    int   cur  = 0;

    // emission/mask prefetch pipeline (distance 4)
    float em0 = embase[1 * C + j], em1 = embase[2 * C + j];
    float em2 = embase[3 * C + j], em3 = embase[4 * C + j];
    float m0 = mbase[1], m1 = mbase[2], m2 = mbase[3], m3 = mbase[4];

    auto step = [&](float em_t, float m_t) {
        const float4* ev = (const float4*)(&sh_e[cur][h * 32]);
        float4 f0  = ev[0];
        float  e0v = f0.x;   // normalizer e_0 (meaningful for h==0 slice only)
        float s0, s1, s2, s3;
        if (m_t != 0.f) {
            s0 = f0.x * uexp[0]; s1 = f0.y * uexp[1];
            s2 = f0.z * uexp[2]; s3 = f0.w * uexp[3];
#pragma unroll
            for (int q = 1; q < 8; ++q) {
                float4 e4 = ev[q];
                s0 = fmaf(e4.x, uexp[4 * q + 0], s0);
                s1 = fmaf(e4.y, uexp[4 * q + 1], s1);
                s2 = fmaf(e4.z, uexp[4 * q + 2], s2);
                s3 = fmaf(e4.w, uexp[4 * q + 3], s3);
            }
        } else {
            // masked step: alpha_new_j = logsumexp_i(alpha_i) for all j
            s0 = f0.x; s1 = f0.y; s2 = f0.z; s3 = f0.w;
#pragma unroll
            for (int q = 1; q < 8; ++q) {
                float4 e4 = ev[q];
                s0 += e4.x; s1 += e4.y; s2 += e4.z; s3 += e4.w;
            }
        }
        float part = (s0 + s1) + (s2 + s3);
        if (h) sh_p[j] = part;
        __syncthreads();
        if (!h) {
            float ssum = part + sh_p[j];
            float r0c  = __fdividef(1.f, e0v);
            base += __logf(e0v);
            float scale = (m_t != 0.f) ? __expf(em_t) * r0c : r0c;
            sh_e[cur ^ 1][j] = ssum * scale;   // e_new = s * exp(em) / e0  (no log/exp on the chain)
        }
        __syncthreads();
        cur ^= 1;
    };

    // t = 1 .. 252 in groups of 4 (prefetch 4 ahead), then 253..255 tail
    for (int t0 = 1; t0 + 3 < S; t0 += 4) {
        step(em0, m0);
        if (t0 + 4 < S) { em0 = embase[(t0 + 4) * C + j]; m0 = mbase[t0 + 4]; }
        step(em1, m1);
        if (t0 + 5 < S) { em1 = embase[(t0 + 5) * C + j]; m1 = mbase[t0 + 5]; }
        step(em2, m2);
        if (t0 + 6 < S) { em2 = embase[(t0 + 6) * C + j]; m2 = mbase[t0 + 6]; }
        step(em3, m3);
        if (t0 + 7 < S) { em3 = embase[(t0 + 7) * C + j]; m3 = mbase[t0 + 7]; }
    }
    step(em0, m0);   // t = 253
    step(em1, m1);   // t = 254
    step(em2, m2);   // t = 255

    // ---------------- finalize: free = log(sum_j e_j) + base ----------------
    if (tid == 0) {
        float sE = 0.f;
#pragma unroll
        for (int k = 0; k < C; ++k) sE += sh_e[cur][k];
        float freeE = __logf(sE) + base;
        float pathE = 0.f;
#pragma unroll
        for (int k = 0; k < 128; ++k) pathE += sh_red[k];
        g_scratch[b] = freeE - pathE;
    }
}

__global__ void crf_reduce(float* __restrict__ out)
{
    float s = 0.f;
#pragma unroll
    for (int k = 0; k < B; ++k) s += g_scratch[k];
    out[0] = s * (1.f / (float)B);
}

extern "C" void kernel_launch(void* const* d_in, const int* in_sizes, int n_in,
                              void* d_out, int out_size)
{
    const float* emis = (const float*)d_in[0];
    const int*   tags = (const int*)d_in[1];
    const float* mask = (const float*)d_in[2];
    const float* U    = (const float*)d_in[3];

    crf_main<<<B, 128>>>(emis, tags, mask, U);
    crf_reduce<<<1, 1>>>((float*)d_out);
}